// round 15
// baseline (speedup 1.0000x reference)
#include <cuda_runtime.h>
#include <cuda_fp16.h>
#include <math.h>
#include <stdint.h>

// ---------------- problem constants ----------------
#define BG    64
#define NA    32
#define HID   600
#define NG    50
#define NL    6
#define NTOT  (BG*NA)      // 2048
#define NE    (BG*NA*NA)   // 65536
#define PGRID 2047         // t = d * PGRID/10 in [0,2047]
#define PTAB  2049         // rows 0..2048
#define TABL  (PTAB*HID)   // per-layer table elems
#define KPAD  64           // padded K for the rbf GEMM
#define W1P_TOT (NL*KPAD*HID)   // 230400
#define INIT_TOT W1P_TOT

// message kernel geometry
#define MP_ACT   150       // active threads (one float4/uint2 quad of the row each)
#define MP_THREADS 160
#define PAIRS    496
#define PAIRS_H  248
// dynamic smem: xs 32*150*8 + ms 32*150*16 + pij 1024 + pu/pw0/pw1 3*1984
#define MSG_SMEM (38400 + 76800 + 1024 + 3*1984)

// ---------------- scratch layout (floats), 64-float aligned regions ----------------
#define AL64(x) (((x) + 63) & ~63)
#define O_H      0
#define O_XJ     AL64(O_H     + NTOT*HID)     // fp16 xj (capacity 2x)
#define O_M      AL64(O_XJ    + NTOT*HID)
#define O_M2     AL64(O_M     + NTOT*HID)     // second partial for message halves
#define O_T1     AL64(O_M2    + NTOT*HID)
#define O_TA_ALL AL64(O_T1    + NTOT*HID)
#define O_TB_ALL AL64(O_TA_ALL + NL*TABL)
#define O_RB64   AL64(O_TB_ALL + (NL*TABL+1)/2)
#define O_W1P    AL64(O_RB64  + PTAB*KPAD)
#define O_EU     AL64(O_W1P   + W1P_TOT)
#define O_EW0    AL64(O_EU    + NE)
#define O_EW1    AL64(O_EW0   + NE)
#define O_POOL   AL64(O_EW1   + NE)
#define SCRATCH_TOT AL64(O_POOL + BG*HID)

__device__ __align__(16) float g_scratch[SCRATCH_TOT];   // ~71 MB static scratch

// ---------------- helpers ----------------
__device__ __forceinline__ float sspf(float x) {
    return fmaxf(x, 0.f) + log1pf(expf(-fabsf(x))) - 0.69314718055994531f;
}
__device__ __forceinline__ uint32_t f2tf(float x) {
    uint32_t r;
    asm("cvt.rna.tf32.f32 %0, %1;" : "=r"(r) : "f"(x));
    return r;
}

#define FL_BIAS 1
#define FL_SSP  2
#define FL_RES  4
#define FL_H16  8
#define FL_ADD2 16

// ---------------- fused init: edges + padded RBF table + padded w1 ----------------
__global__ void init_k(const float* __restrict__ pos, const float* __restrict__ w1,
                       int* __restrict__ eu, float* __restrict__ ew0,
                       float* __restrict__ ew1, float* __restrict__ rb64,
                       float* __restrict__ w1p) {
    int e = blockIdx.x * blockDim.x + threadIdx.x;
    if (e < NE) {
        int b = e >> 10;
        int r = e & 1023;
        int i = r >> 5, j = r & 31;
        int ai = b * NA + i, aj = b * NA + j;
        float dx = pos[ai*3+0] - pos[aj*3+0];
        float dy = pos[ai*3+1] - pos[aj*3+1];
        float dz = pos[ai*3+2] - pos[aj*3+2];
        float sq = dx*dx + dy*dy + dz*dz;
        int   u  = 0;
        float w0 = 0.f, w1v = 0.f;
        if (i != j && sq <= 100.f) {
            float d  = sqrtf(sq > 0.f ? sq : 1.f);
            float cw = 0.5f * (cospif(d * 0.1f) + 1.f);
            float t  = d * ((float)PGRID / 10.f);
            u = (int)t;
            if (u > PGRID) u = PGRID;
            float s = t - (float)u;
            w1v = s * cw;
            w0  = cw - w1v;
        }
        eu[e]  = u;
        ew0[e] = w0;
        ew1[e] = w1v;
    }
    if (e < PTAB * KPAD) {
        int p = e >> 6, g = e & 63;
        float v = 0.f;
        if (g < NG) {
            float d   = (float)p * (10.f / (float)PGRID);
            float off = (float)g * (10.f / 49.f);
            float df  = d - off;
            v = expf(-12.005f * df * df);        // -0.5/(10/49)^2
        }
        rb64[e] = v;
    }
    if (e < W1P_TOT) {
        int L  = e / (KPAD * HID);
        int rr = (e / HID) % KPAD;
        int cc = e % HID;
        w1p[e] = (rr < NG) ? w1[(size_t)L * NG * HID + rr * HID + cc] : 0.f;
    }
}

// ---------------- atom embedding gather ----------------
__global__ void embed_k(const int* __restrict__ z, const float* __restrict__ emb,
                        float* __restrict__ h) {
    int idx = blockIdx.x * blockDim.x + threadIdx.x;
    if (idx >= NTOT * HID) return;
    int n = idx / HID, f = idx % HID;
    h[idx] = emb[z[n] * HID + f];
}

// ---------------- tf32 tensor-core GEMM, pipelined, 8 warps, z-batched ----------------
// C_z = op((A_z (+A2))[M,K] @ W_z[K,N] (+bias_z))
__global__ __launch_bounds__(256) void gemm_tc(
        const float* __restrict__ A, const float* __restrict__ W,
        const float* __restrict__ bias, float* __restrict__ C,
        int M, int N, int K, int flags,
        int zsA, int zsW, int zsB, int zsC, const float* __restrict__ A2) {
    __shared__ uint32_t As[32][72];
    __shared__ uint32_t Bs[32][72];

    int zz = blockIdx.z;
    A += (size_t)zz * zsA;
    W += (size_t)zz * zsW;
    const float* biasz = bias ? bias + (size_t)zz * zsB : bias;
    float*  Cf = C + (size_t)zz * zsC;
    __half* Ch = (__half*)C + (size_t)zz * zsC;

    int tid  = threadIdx.x;
    int row0 = blockIdx.y * 64, col0 = blockIdx.x * 64;
    int warp = tid >> 5, lane = tid & 31;
    int wm = (warp >> 2) * 32;
    int wn = (warp & 3) * 16;
    int g = lane >> 2, tig = lane & 3;

    bool k16 = ((K & 3) == 0);
    bool add2 = (flags & FL_ADD2);

    float c[2][2][4];
#pragma unroll
    for (int mi = 0; mi < 2; mi++)
#pragma unroll
        for (int ni = 0; ni < 2; ni++)
#pragma unroll
            for (int q = 0; q < 4; q++) c[mi][ni][q] = 0.f;

    float a_st[2][4], b_st[2][4];

    auto ldA = [&](int k0) {
#pragma unroll
        for (int l = 0; l < 2; l++) {
            int idx = tid + l * 256;
            int r   = idx >> 3;
            int c4  = idx & 7;
            int grow = row0 + r;
            int kg   = k0 + c4 * 4;
            float v0 = 0.f, v1 = 0.f, v2 = 0.f, v3 = 0.f;
            if (grow < M) {
                if (k16 && (kg + 3 < K)) {
                    float4 t = *(const float4*)(A + (size_t)grow * K + kg);
                    v0 = t.x; v1 = t.y; v2 = t.z; v3 = t.w;
                    if (add2) {
                        float4 s = *(const float4*)(A2 + (size_t)grow * K + kg);
                        v0 += s.x; v1 += s.y; v2 += s.z; v3 += s.w;
                    }
                } else {
                    if (kg + 0 < K) v0 = A[(size_t)grow * K + kg + 0];
                    if (kg + 1 < K) v1 = A[(size_t)grow * K + kg + 1];
                    if (kg + 2 < K) v2 = A[(size_t)grow * K + kg + 2];
                    if (kg + 3 < K) v3 = A[(size_t)grow * K + kg + 3];
                    if (add2) {
                        if (kg + 0 < K) v0 += A2[(size_t)grow * K + kg + 0];
                        if (kg + 1 < K) v1 += A2[(size_t)grow * K + kg + 1];
                        if (kg + 2 < K) v2 += A2[(size_t)grow * K + kg + 2];
                        if (kg + 3 < K) v3 += A2[(size_t)grow * K + kg + 3];
                    }
                }
            }
            a_st[l][0] = v0; a_st[l][1] = v1; a_st[l][2] = v2; a_st[l][3] = v3;
        }
    };
    auto ldB = [&](int k0) {
#pragma unroll
        for (int l = 0; l < 2; l++) {
            int idx = tid + l * 256;
            int kk  = idx >> 4;
            int c16 = idx & 15;
            int kg  = k0 + kk;
            int gc  = col0 + c16 * 4;
            float v0 = 0.f, v1 = 0.f, v2 = 0.f, v3 = 0.f;
            if (kg < K) {
                if (((N & 3) == 0) && (gc + 3 < N)) {
                    float4 t = *(const float4*)(W + (size_t)kg * N + gc);
                    v0 = t.x; v1 = t.y; v2 = t.z; v3 = t.w;
                } else {
                    if (gc + 0 < N) v0 = W[(size_t)kg * N + gc + 0];
                    if (gc + 1 < N) v1 = W[(size_t)kg * N + gc + 1];
                    if (gc + 2 < N) v2 = W[(size_t)kg * N + gc + 2];
                    if (gc + 3 < N) v3 = W[(size_t)kg * N + gc + 3];
                }
            }
            b_st[l][0] = v0; b_st[l][1] = v1; b_st[l][2] = v2; b_st[l][3] = v3;
        }
    };
    auto sts = [&]() {
#pragma unroll
        for (int l = 0; l < 2; l++) {
            int idx = tid + l * 256;
            int r   = idx >> 3;
            int c4  = idx & 7;
#pragma unroll
            for (int q = 0; q < 4; q++) As[c4 * 4 + q][r] = f2tf(a_st[l][q]);
            int kk  = idx >> 4;
            int c16 = idx & 15;
#pragma unroll
            for (int q = 0; q < 4; q++) Bs[kk][c16 * 4 + q] = f2tf(b_st[l][q]);
        }
    };

    int nk = (K + 31) >> 5;

    ldA(0); ldB(0);
    sts();
    __syncthreads();

    for (int kb = 0; kb < nk; kb++) {
        bool more = (kb + 1 < nk);
        if (more) { ldA((kb + 1) << 5); ldB((kb + 1) << 5); }

#pragma unroll
        for (int ks = 0; ks < 4; ks++) {
            int kb8 = ks * 8;
            uint32_t a[2][4], b[2][2];
#pragma unroll
            for (int mi = 0; mi < 2; mi++) {
                int m = wm + mi * 16;
                a[mi][0] = As[kb8 + tig    ][m + g    ];
                a[mi][1] = As[kb8 + tig    ][m + g + 8];
                a[mi][2] = As[kb8 + tig + 4][m + g    ];
                a[mi][3] = As[kb8 + tig + 4][m + g + 8];
            }
#pragma unroll
            for (int ni = 0; ni < 2; ni++) {
                int n = wn + ni * 8;
                b[ni][0] = Bs[kb8 + tig    ][n + g];
                b[ni][1] = Bs[kb8 + tig + 4][n + g];
            }
#pragma unroll
            for (int mi = 0; mi < 2; mi++)
#pragma unroll
                for (int ni = 0; ni < 2; ni++) {
                    asm volatile(
                        "mma.sync.aligned.m16n8k8.row.col.f32.tf32.tf32.f32 "
                        "{%0,%1,%2,%3}, {%4,%5,%6,%7}, {%8,%9}, {%0,%1,%2,%3};\n"
                        : "+f"(c[mi][ni][0]), "+f"(c[mi][ni][1]),
                          "+f"(c[mi][ni][2]), "+f"(c[mi][ni][3])
                        : "r"(a[mi][0]), "r"(a[mi][1]), "r"(a[mi][2]), "r"(a[mi][3]),
                          "r"(b[ni][0]), "r"(b[ni][1]));
                }
        }
        if (more) {
            __syncthreads();
            sts();
            __syncthreads();
        }
    }

    // ---- epilogue: paired even/odd columns ----
#pragma unroll
    for (int mi = 0; mi < 2; mi++) {
#pragma unroll
        for (int h01 = 0; h01 < 2; h01++) {
            int row = row0 + wm + mi * 16 + g + h01 * 8;
            if (row >= M) continue;
#pragma unroll
            for (int ni = 0; ni < 2; ni++) {
                int col = col0 + wn + ni * 8 + tig * 2;
                if (col >= N) continue;
                float v0 = c[mi][ni][h01 * 2 + 0];
                float v1 = c[mi][ni][h01 * 2 + 1];
                if (flags & FL_BIAS) { v0 += biasz[col]; v1 += biasz[col + 1]; }
                if (flags & FL_SSP)  { v0 = sspf(v0);    v1 = sspf(v1); }
                size_t idx = (size_t)row * N + col;
                if (flags & FL_H16) {
                    *(__half2*)(Ch + idx) = __floats2half2_rn(v0, v1);
                } else {
                    if (flags & FL_RES) { v0 += Cf[idx]; v1 += Cf[idx + 1]; }
                    Cf[idx]     = v0;
                    Cf[idx + 1] = v1;
                }
            }
        }
    }
}

// ---------------- pair-symmetric graph-resident message ----------------
// block = (graph, pair-half). All 32 x-rows + 32x600 fp32 accumulators in smem.
// Flat 248-pair loop in diagonal order; wv computed once per unordered pair,
// applied to both directions. Halves write disjoint partial buffers m0/m1.
__global__ __launch_bounds__(MP_THREADS) void message_pair(
        const int* __restrict__ eu, const float* __restrict__ ew0,
        const float* __restrict__ ew1,
        const __half* __restrict__ tab, const __half* __restrict__ xj,
        float* __restrict__ m0, float* __restrict__ m1) {
    extern __shared__ __align__(16) char smem[];
    uint2*  xs  = (uint2*)smem;                               // [32*150]
    float4* ms  = (float4*)(smem + 38400);                    // [32*150]
    unsigned short* pij = (unsigned short*)(smem + 38400 + 76800);  // [496]
    int*    pu  = (int*)  (smem + 38400 + 76800 + 1024);      // [496]
    float*  pw0 = (float*)((char*)pu  + PAIRS * 4);
    float*  pw1 = (float*)((char*)pw0 + PAIRS * 4);

    int blk = blockIdx.x;
    int b   = blk >> 1;
    int hlf = blk & 1;
    int t   = threadIdx.x;

    // pair list (diagonal order) + edge metadata
    for (int p = t; p < PAIRS; p += MP_THREADS) {
        int d = 1, off = 0;
        while (off + (32 - d) <= p) { off += 32 - d; d++; }
        int i = d + (p - off);
        int j = i - d;
        pij[p] = (unsigned short)((i << 8) | j);
        int e = b * 1024 + i * 32 + j;
        pu[p]  = eu[e];
        pw0[p] = ew0[e];
        pw1[p] = ew1[e];
    }
    // x rows (contiguous: 32*150 uint2) + zero accumulators
    const uint2* xrow = (const uint2*)(xj + (size_t)(b * NA) * HID);
    for (int q = t; q < NA * MP_ACT; q += MP_THREADS) {
        xs[q] = xrow[q];
        ms[q] = make_float4(0.f, 0.f, 0.f, 0.f);
    }
    __syncthreads();

    if (t < MP_ACT) {
        const uint2* tab2 = (const uint2*)tab;
        int p0 = hlf * PAIRS_H;
#pragma unroll 4
        for (int pp = 0; pp < PAIRS_H; pp++) {
            int p  = p0 + pp;
            int ij = pij[p];
            int i = ij >> 8, j = ij & 255;
            int u = pu[p];
            float w0 = pw0[p], w1 = pw1[p];
            uint2 t0 = tab2[(size_t)u * MP_ACT + t];
            uint2 t1 = tab2[(size_t)(u + 1) * MP_ACT + t];
            float2 a0 = __half22float2(*(__half2*)&t0.x);
            float2 a1 = __half22float2(*(__half2*)&t0.y);
            float2 b0 = __half22float2(*(__half2*)&t1.x);
            float2 b1 = __half22float2(*(__half2*)&t1.y);
            float4 wv;
            wv.x = fmaf(w0, a0.x, w1 * b0.x);
            wv.y = fmaf(w0, a0.y, w1 * b0.y);
            wv.z = fmaf(w0, a1.x, w1 * b1.x);
            wv.w = fmaf(w0, a1.y, w1 * b1.y);
            uint2 xjq = xs[j * MP_ACT + t];
            uint2 xiq = xs[i * MP_ACT + t];
            float2 xj0 = __half22float2(*(__half2*)&xjq.x);
            float2 xj1 = __half22float2(*(__half2*)&xjq.y);
            float2 xi0 = __half22float2(*(__half2*)&xiq.x);
            float2 xi1 = __half22float2(*(__half2*)&xiq.y);
            float4 mi = ms[i * MP_ACT + t];
            mi.x = fmaf(wv.x, xj0.x, mi.x);
            mi.y = fmaf(wv.y, xj0.y, mi.y);
            mi.z = fmaf(wv.z, xj1.x, mi.z);
            mi.w = fmaf(wv.w, xj1.y, mi.w);
            ms[i * MP_ACT + t] = mi;
            float4 mj = ms[j * MP_ACT + t];
            mj.x = fmaf(wv.x, xi0.x, mj.x);
            mj.y = fmaf(wv.y, xi0.y, mj.y);
            mj.z = fmaf(wv.z, xi1.x, mj.z);
            mj.w = fmaf(wv.w, xi1.y, mj.w);
            ms[j * MP_ACT + t] = mj;
        }
    }
    __syncthreads();

    // plain-store writeout of this half's partial sums
    float* dst = (hlf == 0 ? m0 : m1) + (size_t)(b * NA) * HID;
    for (int q = t; q < NA * MP_ACT; q += MP_THREADS) {
        *(float4*)(dst + (q / MP_ACT) * HID + (q % MP_ACT) * 4) = ms[q];
    }
}

// ---------------- per-graph mean pool ----------------
__global__ void pool_k(const float* __restrict__ h, float* __restrict__ pool) {
    int idx = blockIdx.x * blockDim.x + threadIdx.x;
    if (idx >= BG * HID) return;
    int b = idx / HID, f = idx % HID;
    float s = 0.f;
#pragma unroll
    for (int i = 0; i < NA; i++) s += h[(size_t)(b * NA + i) * HID + f];
    pool[idx] = s * (1.f / (float)NA);
}

// ---------------- host launch ----------------
extern "C" void kernel_launch(void* const* d_in, const int* in_sizes, int n_in,
                              void* d_out, int out_size) {
    const int*   z    = (const int*)  d_in[0];
    const float* pos  = (const float*)d_in[1];
    const float* emb  = (const float*)d_in[3];
    const float* w1   = (const float*)d_in[4];
    const float* b1   = (const float*)d_in[5];
    const float* w2   = (const float*)d_in[6];
    const float* b2   = (const float*)d_in[7];
    const float* l1w  = (const float*)d_in[8];
    const float* l2w  = (const float*)d_in[9];
    const float* l2b  = (const float*)d_in[10];
    const float* lw   = (const float*)d_in[11];
    const float* lb   = (const float*)d_in[12];
    const float* pw   = (const float*)d_in[13];
    const float* pb   = (const float*)d_in[14];
    float* out = (float*)d_out;

    float* S = nullptr;
    cudaGetSymbolAddress((void**)&S, g_scratch);
    float*  H   = S + O_H;
    __half* XJh = (__half*)(S + O_XJ);
    float*  MM  = S + O_M;
    float*  M2  = S + O_M2;
    float*  T1  = S + O_T1;
    float*  TAa = S + O_TA_ALL;
    __half* TBa = (__half*)(S + O_TB_ALL);
    float*  RB  = S + O_RB64;
    float*  W1P = S + O_W1P;
    int*    EU  = (int*)(S + O_EU);
    float*  E0  = S + O_EW0;
    float*  E1  = S + O_EW1;
    float*  PL  = S + O_POOL;

    static bool attr_set = false;
    if (!attr_set) {
        cudaFuncSetAttribute(message_pair,
                             cudaFuncAttributeMaxDynamicSharedMemorySize, MSG_SMEM);
        attr_set = true;
    }

    init_k <<<(INIT_TOT + 255) / 256, 256>>>(pos, w1, EU, E0, E1, RB, W1P);
    embed_k<<<(NTOT * HID + 255) / 256, 256>>>(z, emb, H);

    dim3 gN((HID + 63) / 64, (NTOT + 63) / 64);        // (10, 32)
    dim3 gTB((HID + 63) / 64, (PTAB + 63) / 64, NL);   // (10, 33, 6) batched

    // ---- all-layer filter-table build (2 launches) ----
    gemm_tc<<<gTB, 256>>>(RB, W1P, b1, TAa, PTAB, HID, KPAD, FL_BIAS | FL_SSP,
                          0, KPAD * HID, HID, TABL, nullptr);
    gemm_tc<<<gTB, 256>>>(TAa, w2, b2, (float*)TBa, PTAB, HID, HID,
                          FL_BIAS | FL_H16, TABL, HID * HID, HID, TABL, nullptr);

    for (int L = 0; L < NL; L++) {
        const float* l1wL = l1w + (size_t)L * HID * HID;
        const float* l2wL = l2w + (size_t)L * HID * HID;
        const float* l2bL = l2b + (size_t)L * HID;
        const float* lwL  = lw  + (size_t)L * HID * HID;
        const float* lbL  = lb  + (size_t)L * HID;
        const __half* tabL = TBa + (size_t)L * TABL;

        // xj = fp16(h @ lin1) (no bias)
        gemm_tc<<<gN, 256>>>(H, l1wL, nullptr, (float*)XJh, NTOT, HID, HID,
                             FL_H16, 0, 0, 0, 0, nullptr);
        // pair-symmetric message: halves write MM / M2 partials
        message_pair<<<BG * 2, MP_THREADS, MSG_SMEM>>>(EU, E0, E1, tabL, XJh,
                                                       MM, M2);
        // v = ssp((MM+M2) @ l2w + l2b) @ lw + lb ; h += v
        gemm_tc<<<gN, 256>>>(MM, l2wL, l2bL, T1, NTOT, HID, HID,
                             FL_BIAS | FL_SSP | FL_ADD2, 0, 0, 0, 0, M2);
        gemm_tc<<<gN, 256>>>(T1, lwL,  lbL,  H,  NTOT, HID, HID,
                             FL_BIAS | FL_RES, 0, 0, 0, 0, nullptr);
    }

    pool_k<<<(BG * HID + 255) / 256, 256>>>(H, PL);
    gemm_tc<<<dim3((HID + 63) / 64, 1), 256>>>(PL, pw, pb, out, BG, HID, HID,
                                               FL_BIAS, 0, 0, 0, 0, nullptr);
}

// round 16
// speedup vs baseline: 1.1931x; 1.1931x over previous
#include <cuda_runtime.h>
#include <cuda_fp16.h>
#include <math.h>
#include <stdint.h>

// ---------------- problem constants ----------------
#define BG    64
#define NA    32
#define HID   600
#define NG    50
#define NL    6
#define NTOT  (BG*NA)      // 2048
#define NE    (BG*NA*NA)   // 65536
#define PGRID 2047         // t = d * PGRID/10 in [0,2047]
#define PTAB  2049         // rows 0..2048
#define TABL  (PTAB*HID)   // per-layer table elems
#define KPAD  64           // padded K for the rbf GEMM
#define W1P_TOT (NL*KPAD*HID)   // 230400
#define INIT_TOT W1P_TOT

// ---------------- scratch layout (floats), 64-float aligned regions ----------------
#define AL64(x) (((x) + 63) & ~63)
#define O_H      0
#define O_XJ     AL64(O_H     + NTOT*HID)     // fp16 xj (capacity 2x)
#define O_M      AL64(O_XJ    + NTOT*HID)
#define O_T1     AL64(O_M     + NTOT*HID)
#define O_TA_ALL AL64(O_T1    + NTOT*HID)
#define O_TB_ALL AL64(O_TA_ALL + NL*TABL)
#define O_RB64   AL64(O_TB_ALL + (NL*TABL+1)/2)
#define O_W1P    AL64(O_RB64  + PTAB*KPAD)
#define O_EU     AL64(O_W1P   + W1P_TOT)
#define O_EW0    AL64(O_EU    + NE)
#define O_EW1    AL64(O_EW0   + NE)
#define O_POOL   AL64(O_EW1   + NE)
#define SCRATCH_TOT AL64(O_POOL + BG*HID)

__device__ __align__(16) float g_scratch[SCRATCH_TOT];   // ~66 MB static scratch

// ---------------- helpers ----------------
__device__ __forceinline__ float sspf(float x) {
    return fmaxf(x, 0.f) + log1pf(expf(-fabsf(x))) - 0.69314718055994531f;
}
__device__ __forceinline__ uint32_t f2tf(float x) {
    uint32_t r;
    asm("cvt.rna.tf32.f32 %0, %1;" : "=r"(r) : "f"(x));
    return r;
}

#define FL_BIAS 1
#define FL_SSP  2
#define FL_RES  4
#define FL_H16  8

// ---------------- fused init: edges + padded RBF table + padded w1 ----------------
__global__ void init_k(const float* __restrict__ pos, const float* __restrict__ w1,
                       int* __restrict__ eu, float* __restrict__ ew0,
                       float* __restrict__ ew1, float* __restrict__ rb64,
                       float* __restrict__ w1p) {
    int e = blockIdx.x * blockDim.x + threadIdx.x;
    if (e < NE) {
        int b = e >> 10;
        int r = e & 1023;
        int i = r >> 5, j = r & 31;
        int ai = b * NA + i, aj = b * NA + j;
        float dx = pos[ai*3+0] - pos[aj*3+0];
        float dy = pos[ai*3+1] - pos[aj*3+1];
        float dz = pos[ai*3+2] - pos[aj*3+2];
        float sq = dx*dx + dy*dy + dz*dz;
        int   u  = 0;
        float w0 = 0.f, w1v = 0.f;
        if (i != j && sq <= 100.f) {
            float d  = sqrtf(sq > 0.f ? sq : 1.f);
            float cw = 0.5f * (cospif(d * 0.1f) + 1.f);
            float t  = d * ((float)PGRID / 10.f);
            u = (int)t;
            if (u > PGRID) u = PGRID;
            float s = t - (float)u;
            w1v = s * cw;
            w0  = cw - w1v;
        }
        eu[e]  = u;
        ew0[e] = w0;
        ew1[e] = w1v;
    }
    if (e < PTAB * KPAD) {
        int p = e >> 6, g = e & 63;
        float v = 0.f;
        if (g < NG) {
            float d   = (float)p * (10.f / (float)PGRID);
            float off = (float)g * (10.f / 49.f);
            float df  = d - off;
            v = expf(-12.005f * df * df);        // -0.5/(10/49)^2
        }
        rb64[e] = v;
    }
    if (e < W1P_TOT) {
        int L  = e / (KPAD * HID);
        int rr = (e / HID) % KPAD;
        int cc = e % HID;
        w1p[e] = (rr < NG) ? w1[(size_t)L * NG * HID + rr * HID + cc] : 0.f;
    }
}

// ---------------- atom embedding gather ----------------
__global__ void embed_k(const int* __restrict__ z, const float* __restrict__ emb,
                        float* __restrict__ h) {
    int idx = blockIdx.x * blockDim.x + threadIdx.x;
    if (idx >= NTOT * HID) return;
    int n = idx / HID, f = idx % HID;
    h[idx] = emb[z[n] * HID + f];
}

// ---------------- 64x64 tf32 GEMM, pipelined, z-batched (table build) ----------------
__global__ __launch_bounds__(256) void gemm_tc(
        const float* __restrict__ A, const float* __restrict__ W,
        const float* __restrict__ bias, float* __restrict__ C,
        int M, int N, int K, int flags,
        int zsA, int zsW, int zsB, int zsC) {
    __shared__ uint32_t As[32][72];
    __shared__ uint32_t Bs[32][72];

    int zz = blockIdx.z;
    A += (size_t)zz * zsA;
    W += (size_t)zz * zsW;
    const float* biasz = bias ? bias + (size_t)zz * zsB : bias;
    float*  Cf = C + (size_t)zz * zsC;
    __half* Ch = (__half*)C + (size_t)zz * zsC;

    int tid  = threadIdx.x;
    int row0 = blockIdx.y * 64, col0 = blockIdx.x * 64;
    int warp = tid >> 5, lane = tid & 31;
    int wm = (warp >> 2) * 32;
    int wn = (warp & 3) * 16;
    int g = lane >> 2, tig = lane & 3;

    bool k16 = ((K & 3) == 0);

    float c[2][2][4];
#pragma unroll
    for (int mi = 0; mi < 2; mi++)
#pragma unroll
        for (int ni = 0; ni < 2; ni++)
#pragma unroll
            for (int q = 0; q < 4; q++) c[mi][ni][q] = 0.f;

    float a_st[2][4], b_st[2][4];

    auto ldA = [&](int k0) {
#pragma unroll
        for (int l = 0; l < 2; l++) {
            int idx = tid + l * 256;
            int r   = idx >> 3;
            int c4  = idx & 7;
            int grow = row0 + r;
            int kg   = k0 + c4 * 4;
            float v0 = 0.f, v1 = 0.f, v2 = 0.f, v3 = 0.f;
            if (grow < M) {
                if (k16 && (kg + 3 < K)) {
                    float4 t = *(const float4*)(A + (size_t)grow * K + kg);
                    v0 = t.x; v1 = t.y; v2 = t.z; v3 = t.w;
                } else {
                    if (kg + 0 < K) v0 = A[(size_t)grow * K + kg + 0];
                    if (kg + 1 < K) v1 = A[(size_t)grow * K + kg + 1];
                    if (kg + 2 < K) v2 = A[(size_t)grow * K + kg + 2];
                    if (kg + 3 < K) v3 = A[(size_t)grow * K + kg + 3];
                }
            }
            a_st[l][0] = v0; a_st[l][1] = v1; a_st[l][2] = v2; a_st[l][3] = v3;
        }
    };
    auto ldB = [&](int k0) {
#pragma unroll
        for (int l = 0; l < 2; l++) {
            int idx = tid + l * 256;
            int kk  = idx >> 4;
            int c16 = idx & 15;
            int kg  = k0 + kk;
            int gc  = col0 + c16 * 4;
            float v0 = 0.f, v1 = 0.f, v2 = 0.f, v3 = 0.f;
            if (kg < K) {
                if (((N & 3) == 0) && (gc + 3 < N)) {
                    float4 t = *(const float4*)(W + (size_t)kg * N + gc);
                    v0 = t.x; v1 = t.y; v2 = t.z; v3 = t.w;
                } else {
                    if (gc + 0 < N) v0 = W[(size_t)kg * N + gc + 0];
                    if (gc + 1 < N) v1 = W[(size_t)kg * N + gc + 1];
                    if (gc + 2 < N) v2 = W[(size_t)kg * N + gc + 2];
                    if (gc + 3 < N) v3 = W[(size_t)kg * N + gc + 3];
                }
            }
            b_st[l][0] = v0; b_st[l][1] = v1; b_st[l][2] = v2; b_st[l][3] = v3;
        }
    };
    auto sts = [&]() {
#pragma unroll
        for (int l = 0; l < 2; l++) {
            int idx = tid + l * 256;
            int r   = idx >> 3;
            int c4  = idx & 7;
#pragma unroll
            for (int q = 0; q < 4; q++) As[c4 * 4 + q][r] = f2tf(a_st[l][q]);
            int kk  = idx >> 4;
            int c16 = idx & 15;
#pragma unroll
            for (int q = 0; q < 4; q++) Bs[kk][c16 * 4 + q] = f2tf(b_st[l][q]);
        }
    };

    int nk = (K + 31) >> 5;

    ldA(0); ldB(0);
    sts();
    __syncthreads();

    for (int kb = 0; kb < nk; kb++) {
        bool more = (kb + 1 < nk);
        if (more) { ldA((kb + 1) << 5); ldB((kb + 1) << 5); }

#pragma unroll
        for (int ks = 0; ks < 4; ks++) {
            int kb8 = ks * 8;
            uint32_t a[2][4], b[2][2];
#pragma unroll
            for (int mi = 0; mi < 2; mi++) {
                int m = wm + mi * 16;
                a[mi][0] = As[kb8 + tig    ][m + g    ];
                a[mi][1] = As[kb8 + tig    ][m + g + 8];
                a[mi][2] = As[kb8 + tig + 4][m + g    ];
                a[mi][3] = As[kb8 + tig + 4][m + g + 8];
            }
#pragma unroll
            for (int ni = 0; ni < 2; ni++) {
                int n = wn + ni * 8;
                b[ni][0] = Bs[kb8 + tig    ][n + g];
                b[ni][1] = Bs[kb8 + tig + 4][n + g];
            }
#pragma unroll
            for (int mi = 0; mi < 2; mi++)
#pragma unroll
                for (int ni = 0; ni < 2; ni++) {
                    asm volatile(
                        "mma.sync.aligned.m16n8k8.row.col.f32.tf32.tf32.f32 "
                        "{%0,%1,%2,%3}, {%4,%5,%6,%7}, {%8,%9}, {%0,%1,%2,%3};\n"
                        : "+f"(c[mi][ni][0]), "+f"(c[mi][ni][1]),
                          "+f"(c[mi][ni][2]), "+f"(c[mi][ni][3])
                        : "r"(a[mi][0]), "r"(a[mi][1]), "r"(a[mi][2]), "r"(a[mi][3]),
                          "r"(b[ni][0]), "r"(b[ni][1]));
                }
        }
        if (more) {
            __syncthreads();
            sts();
            __syncthreads();
        }
    }

#pragma unroll
    for (int mi = 0; mi < 2; mi++) {
#pragma unroll
        for (int h01 = 0; h01 < 2; h01++) {
            int row = row0 + wm + mi * 16 + g + h01 * 8;
            if (row >= M) continue;
#pragma unroll
            for (int ni = 0; ni < 2; ni++) {
                int col = col0 + wn + ni * 8 + tig * 2;
                if (col >= N) continue;
                float v0 = c[mi][ni][h01 * 2 + 0];
                float v1 = c[mi][ni][h01 * 2 + 1];
                if (flags & FL_BIAS) { v0 += biasz[col]; v1 += biasz[col + 1]; }
                if (flags & FL_SSP)  { v0 = sspf(v0);    v1 = sspf(v1); }
                size_t idx = (size_t)row * N + col;
                if (flags & FL_H16) {
                    *(__half2*)(Ch + idx) = __floats2half2_rn(v0, v1);
                } else {
                    if (flags & FL_RES) { v0 += Cf[idx]; v1 += Cf[idx + 1]; }
                    Cf[idx]     = v0;
                    Cf[idx + 1] = v1;
                }
            }
        }
    }
}

// ---------------- 32x64 tf32 GEMM (node GEMMs: grid 640, 4+ CTAs/SM) ----------------
// C = op(A[M,K] @ W[K,N] (+bias)) ; BM=32, BN=64, BK=32, 8 warps 2x4 (16x16 each)
__global__ __launch_bounds__(256) void gemm32(
        const float* __restrict__ A, const float* __restrict__ W,
        const float* __restrict__ bias, float* __restrict__ C,
        int M, int N, int K, int flags) {
    __shared__ uint32_t As[32][40];   // [k][m], pad 8 -> conflict-free
    __shared__ uint32_t Bs[32][72];   // [k][n]

    int tid  = threadIdx.x;
    int row0 = blockIdx.y * 32, col0 = blockIdx.x * 64;
    int warp = tid >> 5, lane = tid & 31;
    int wm = (warp >> 2) * 16;        // 2 m-rows of 16
    int wn = (warp & 3) * 16;         // 4 n-cols of 16
    int g = lane >> 2, tig = lane & 3;

    float c[2][4];
#pragma unroll
    for (int ni = 0; ni < 2; ni++)
#pragma unroll
        for (int q = 0; q < 4; q++) c[ni][q] = 0.f;

    float a_st[4], b_st[2][4];

    auto ldA = [&](int k0) {
        int r   = tid >> 3;           // 0..31
        int c4  = tid & 7;
        int grow = row0 + r;
        int kg   = k0 + c4 * 4;
        float v0 = 0.f, v1 = 0.f, v2 = 0.f, v3 = 0.f;
        if (grow < M && kg + 3 < K) {
            float4 t = *(const float4*)(A + (size_t)grow * K + kg);
            v0 = t.x; v1 = t.y; v2 = t.z; v3 = t.w;
        } else if (grow < M) {
            if (kg + 0 < K) v0 = A[(size_t)grow * K + kg + 0];
            if (kg + 1 < K) v1 = A[(size_t)grow * K + kg + 1];
            if (kg + 2 < K) v2 = A[(size_t)grow * K + kg + 2];
            if (kg + 3 < K) v3 = A[(size_t)grow * K + kg + 3];
        }
        a_st[0] = v0; a_st[1] = v1; a_st[2] = v2; a_st[3] = v3;
    };
    auto ldB = [&](int k0) {
#pragma unroll
        for (int l = 0; l < 2; l++) {
            int idx = tid + l * 256;
            int kk  = idx >> 4;
            int c16 = idx & 15;
            int kg  = k0 + kk;
            int gc  = col0 + c16 * 4;
            float v0 = 0.f, v1 = 0.f, v2 = 0.f, v3 = 0.f;
            if (kg < K) {
                if (gc + 3 < N) {
                    float4 t = *(const float4*)(W + (size_t)kg * N + gc);
                    v0 = t.x; v1 = t.y; v2 = t.z; v3 = t.w;
                } else {
                    if (gc + 0 < N) v0 = W[(size_t)kg * N + gc + 0];
                    if (gc + 1 < N) v1 = W[(size_t)kg * N + gc + 1];
                    if (gc + 2 < N) v2 = W[(size_t)kg * N + gc + 2];
                    if (gc + 3 < N) v3 = W[(size_t)kg * N + gc + 3];
                }
            }
            b_st[l][0] = v0; b_st[l][1] = v1; b_st[l][2] = v2; b_st[l][3] = v3;
        }
    };
    auto sts = [&]() {
        int r  = tid >> 3;
        int c4 = tid & 7;
#pragma unroll
        for (int q = 0; q < 4; q++) As[c4 * 4 + q][r] = f2tf(a_st[q]);
#pragma unroll
        for (int l = 0; l < 2; l++) {
            int idx = tid + l * 256;
            int kk  = idx >> 4;
            int c16 = idx & 15;
#pragma unroll
            for (int q = 0; q < 4; q++) Bs[kk][c16 * 4 + q] = f2tf(b_st[l][q]);
        }
    };

    int nk = (K + 31) >> 5;

    ldA(0); ldB(0);
    sts();
    __syncthreads();

    for (int kb = 0; kb < nk; kb++) {
        bool more = (kb + 1 < nk);
        if (more) { ldA((kb + 1) << 5); ldB((kb + 1) << 5); }

#pragma unroll
        for (int ks = 0; ks < 4; ks++) {
            int kb8 = ks * 8;
            uint32_t a[4], b[2][2];
            a[0] = As[kb8 + tig    ][wm + g    ];
            a[1] = As[kb8 + tig    ][wm + g + 8];
            a[2] = As[kb8 + tig + 4][wm + g    ];
            a[3] = As[kb8 + tig + 4][wm + g + 8];
#pragma unroll
            for (int ni = 0; ni < 2; ni++) {
                int n = wn + ni * 8;
                b[ni][0] = Bs[kb8 + tig    ][n + g];
                b[ni][1] = Bs[kb8 + tig + 4][n + g];
            }
#pragma unroll
            for (int ni = 0; ni < 2; ni++) {
                asm volatile(
                    "mma.sync.aligned.m16n8k8.row.col.f32.tf32.tf32.f32 "
                    "{%0,%1,%2,%3}, {%4,%5,%6,%7}, {%8,%9}, {%0,%1,%2,%3};\n"
                    : "+f"(c[ni][0]), "+f"(c[ni][1]),
                      "+f"(c[ni][2]), "+f"(c[ni][3])
                    : "r"(a[0]), "r"(a[1]), "r"(a[2]), "r"(a[3]),
                      "r"(b[ni][0]), "r"(b[ni][1]));
            }
        }
        if (more) {
            __syncthreads();
            sts();
            __syncthreads();
        }
    }

#pragma unroll
    for (int h01 = 0; h01 < 2; h01++) {
        int row = row0 + wm + g + h01 * 8;
        if (row >= M) continue;
#pragma unroll
        for (int ni = 0; ni < 2; ni++) {
            int col = col0 + wn + ni * 8 + tig * 2;
            if (col >= N) continue;
            float v0 = c[ni][h01 * 2 + 0];
            float v1 = c[ni][h01 * 2 + 1];
            if (flags & FL_BIAS) { v0 += bias[col]; v1 += bias[col + 1]; }
            if (flags & FL_SSP)  { v0 = sspf(v0);   v1 = sspf(v1); }
            size_t idx = (size_t)row * N + col;
            if (flags & FL_H16) {
                *(__half2*)((__half*)C + idx) = __floats2half2_rn(v0, v1);
            } else {
                if (flags & FL_RES) { v0 += C[idx]; v1 += C[idx + 1]; }
                C[idx]     = v0;
                C[idx + 1] = v1;
            }
        }
    }
}

// ---------------- message: fp16 table + fp16 x, direct-LDG (R14 best) ----------------
__global__ __launch_bounds__(128) void message_h(
        const int* __restrict__ eu, const float* __restrict__ ew0,
        const float* __restrict__ ew1,
        const __half* __restrict__ tab, const __half* __restrict__ xj,
        float* __restrict__ m) {
    int bi = blockIdx.x;
    int b  = bi >> 5;
    int tid = threadIdx.x;

    __shared__ int   us[NA];
    __shared__ float w0s[NA], w1s[NA];
    if (tid < NA) {
        int e = bi * NA + tid;
        us[tid]  = eu[e];
        w0s[tid] = ew0[e];
        w1s[tid] = ew1[e];
    }
    __syncthreads();

    float4 acc0 = make_float4(0.f, 0.f, 0.f, 0.f);
    float4 acc1 = make_float4(0.f, 0.f, 0.f, 0.f);
    const __half* xb = xj + (size_t)(b * NA) * HID;

#pragma unroll 4
    for (int j = 0; j < NA; j++) {
        int   u  = us[j];
        float w0 = w0s[j], w1 = w1s[j];
        const __half* T0 = tab + (size_t)u * HID;
        const __half* xr = xb + (size_t)j * HID;
        {
            uint2 r0 = *(const uint2*)(T0 + tid * 4);
            uint2 r1 = *(const uint2*)(T0 + HID + tid * 4);
            uint2 xw = *(const uint2*)(xr + tid * 4);
            float2 a0 = __half22float2(*(__half2*)&r0.x);
            float2 a1 = __half22float2(*(__half2*)&r0.y);
            float2 b0 = __half22float2(*(__half2*)&r1.x);
            float2 b1 = __half22float2(*(__half2*)&r1.y);
            float2 x0 = __half22float2(*(__half2*)&xw.x);
            float2 x1 = __half22float2(*(__half2*)&xw.y);
            acc0.x = fmaf(fmaf(w0, a0.x, w1 * b0.x), x0.x, acc0.x);
            acc0.y = fmaf(fmaf(w0, a0.y, w1 * b0.y), x0.y, acc0.y);
            acc0.z = fmaf(fmaf(w0, a1.x, w1 * b1.x), x1.x, acc0.z);
            acc0.w = fmaf(fmaf(w0, a1.y, w1 * b1.y), x1.y, acc0.w);
        }
        if (tid < 22) {
            int q = tid + 128;
            uint2 r0 = *(const uint2*)(T0 + q * 4);
            uint2 r1 = *(const uint2*)(T0 + HID + q * 4);
            uint2 xw = *(const uint2*)(xr + q * 4);
            float2 a0 = __half22float2(*(__half2*)&r0.x);
            float2 a1 = __half22float2(*(__half2*)&r0.y);
            float2 b0 = __half22float2(*(__half2*)&r1.x);
            float2 b1 = __half22float2(*(__half2*)&r1.y);
            float2 x0 = __half22float2(*(__half2*)&xw.x);
            float2 x1 = __half22float2(*(__half2*)&xw.y);
            acc1.x = fmaf(fmaf(w0, a0.x, w1 * b0.x), x0.x, acc1.x);
            acc1.y = fmaf(fmaf(w0, a0.y, w1 * b0.y), x0.y, acc1.y);
            acc1.z = fmaf(fmaf(w0, a1.x, w1 * b1.x), x1.x, acc1.z);
            acc1.w = fmaf(fmaf(w0, a1.y, w1 * b1.y), x1.y, acc1.w);
        }
    }
    float4* mr = (float4*)(m + (size_t)bi * HID);
    mr[tid] = acc0;
    if (tid < 22) mr[tid + 128] = acc1;
}

// ---------------- per-graph mean pool ----------------
__global__ void pool_k(const float* __restrict__ h, float* __restrict__ pool) {
    int idx = blockIdx.x * blockDim.x + threadIdx.x;
    if (idx >= BG * HID) return;
    int b = idx / HID, f = idx % HID;
    float s = 0.f;
#pragma unroll
    for (int i = 0; i < NA; i++) s += h[(size_t)(b * NA + i) * HID + f];
    pool[idx] = s * (1.f / (float)NA);
}

// ---------------- host launch ----------------
extern "C" void kernel_launch(void* const* d_in, const int* in_sizes, int n_in,
                              void* d_out, int out_size) {
    const int*   z    = (const int*)  d_in[0];
    const float* pos  = (const float*)d_in[1];
    const float* emb  = (const float*)d_in[3];
    const float* w1   = (const float*)d_in[4];
    const float* b1   = (const float*)d_in[5];
    const float* w2   = (const float*)d_in[6];
    const float* b2   = (const float*)d_in[7];
    const float* l1w  = (const float*)d_in[8];
    const float* l2w  = (const float*)d_in[9];
    const float* l2b  = (const float*)d_in[10];
    const float* lw   = (const float*)d_in[11];
    const float* lb   = (const float*)d_in[12];
    const float* pw   = (const float*)d_in[13];
    const float* pb   = (const float*)d_in[14];
    float* out = (float*)d_out;

    float* S = nullptr;
    cudaGetSymbolAddress((void**)&S, g_scratch);
    float*  H   = S + O_H;
    __half* XJh = (__half*)(S + O_XJ);
    float*  MM  = S + O_M;
    float*  T1  = S + O_T1;
    float*  TAa = S + O_TA_ALL;
    __half* TBa = (__half*)(S + O_TB_ALL);
    float*  RB  = S + O_RB64;
    float*  W1P = S + O_W1P;
    int*    EU  = (int*)(S + O_EU);
    float*  E0  = S + O_EW0;
    float*  E1  = S + O_EW1;
    float*  PL  = S + O_POOL;

    init_k <<<(INIT_TOT + 255) / 256, 256>>>(pos, w1, EU, E0, E1, RB, W1P);
    embed_k<<<(NTOT * HID + 255) / 256, 256>>>(z, emb, H);

    dim3 gN32((HID + 63) / 64, (NTOT + 31) / 32);      // (10, 64) = 640 blocks
    dim3 gTB((HID + 63) / 64, (PTAB + 63) / 64, NL);   // (10, 33, 6) batched

    // ---- all-layer filter-table build (2 launches) ----
    gemm_tc<<<gTB, 256>>>(RB, W1P, b1, TAa, PTAB, HID, KPAD, FL_BIAS | FL_SSP,
                          0, KPAD * HID, HID, TABL);
    gemm_tc<<<gTB, 256>>>(TAa, w2, b2, (float*)TBa, PTAB, HID, HID,
                          FL_BIAS | FL_H16, TABL, HID * HID, HID, TABL);

    for (int L = 0; L < NL; L++) {
        const float* l1wL = l1w + (size_t)L * HID * HID;
        const float* l2wL = l2w + (size_t)L * HID * HID;
        const float* l2bL = l2b + (size_t)L * HID;
        const float* lwL  = lw  + (size_t)L * HID * HID;
        const float* lbL  = lb  + (size_t)L * HID;
        const __half* tabL = TBa + (size_t)L * TABL;

        // xj = fp16(h @ lin1) (no bias)
        gemm32<<<gN32, 256>>>(H, l1wL, nullptr, (float*)XJh, NTOT, HID, HID, FL_H16);
        // fp16 interpolate + scatter-reduce message
        message_h<<<NTOT, 128>>>(EU, E0, E1, tabL, XJh, MM);
        // v = ssp(m @ l2w + l2b) @ lw + lb ; h += v
        gemm32<<<gN32, 256>>>(MM, l2wL, l2bL, T1, NTOT, HID, HID, FL_BIAS | FL_SSP);
        gemm32<<<gN32, 256>>>(T1, lwL,  lbL,  H,  NTOT, HID, HID, FL_BIAS | FL_RES);
    }

    pool_k<<<(BG * HID + 255) / 256, 256>>>(H, PL);
    gemm32<<<dim3((HID + 63) / 64, 2), 256>>>(PL, pw, pb, out, BG, HID, HID, FL_BIAS);
}

// round 17
// speedup vs baseline: 1.3038x; 1.0928x over previous
#include <cuda_runtime.h>
#include <cuda_fp16.h>
#include <math.h>
#include <stdint.h>

// ---------------- problem constants ----------------
#define BG    64
#define NA    32
#define HID   600
#define NG    50
#define NL    6
#define NTOT  (BG*NA)      // 2048
#define NE    (BG*NA*NA)   // 65536
#define PGRID 1023         // t = d * PGRID/10 in [0,1023]
#define PTAB  1025         // rows 0..1024
#define TABL  (PTAB*HID)   // per-layer table elems
#define KPAD  64           // padded K for the rbf GEMM
#define W1P_TOT (NL*KPAD*HID)   // 230400
#define INIT_TOT W1P_TOT        // > NE, > PTAB*KPAD

// ---------------- scratch layout (floats), 64-float aligned regions ----------------
#define AL64(x) (((x) + 63) & ~63)
#define O_H      0
#define O_XJ     AL64(O_H     + NTOT*HID)     // fp16 xj (capacity 2x)
#define O_M      AL64(O_XJ    + NTOT*HID)
#define O_T1     AL64(O_M     + NTOT*HID)
#define O_TA_ALL AL64(O_T1    + NTOT*HID)     // fp32 TA for ALL layers
#define O_TB_ALL AL64(O_TA_ALL + NL*TABL)     // fp16 table for ALL layers
#define O_RB64   AL64(O_TB_ALL + (NL*TABL+1)/2)
#define O_W1P    AL64(O_RB64  + PTAB*KPAD)
#define O_EU     AL64(O_W1P   + W1P_TOT)
#define O_EW0    AL64(O_EU    + NE)
#define O_EW1    AL64(O_EW0   + NE)
#define O_POOL   AL64(O_EW1   + NE)
#define SCRATCH_TOT AL64(O_POOL + BG*HID)

__device__ __align__(16) float g_scratch[SCRATCH_TOT];   // ~45 MB static scratch

// ---------------- helpers ----------------
__device__ __forceinline__ float sspf(float x) {
    return fmaxf(x, 0.f) + log1pf(expf(-fabsf(x))) - 0.69314718055994531f;
}
__device__ __forceinline__ uint32_t f2tf(float x) {
    uint32_t r;
    asm("cvt.rna.tf32.f32 %0, %1;" : "=r"(r) : "f"(x));
    return r;
}

#define FL_BIAS 1
#define FL_SSP  2
#define FL_RES  4
#define FL_H16  8

// ---------------- fused init: edges + padded RBF table + padded w1 ----------------
__global__ void init_k(const float* __restrict__ pos, const float* __restrict__ w1,
                       int* __restrict__ eu, float* __restrict__ ew0,
                       float* __restrict__ ew1, float* __restrict__ rb64,
                       float* __restrict__ w1p) {
    int e = blockIdx.x * blockDim.x + threadIdx.x;
    if (e < NE) {
        int b = e >> 10;
        int r = e & 1023;
        int i = r >> 5, j = r & 31;
        int ai = b * NA + i, aj = b * NA + j;
        float dx = pos[ai*3+0] - pos[aj*3+0];
        float dy = pos[ai*3+1] - pos[aj*3+1];
        float dz = pos[ai*3+2] - pos[aj*3+2];
        float sq = dx*dx + dy*dy + dz*dz;
        int   u  = 0;
        float w0 = 0.f, w1v = 0.f;
        if (i != j && sq <= 100.f) {
            float d  = sqrtf(sq > 0.f ? sq : 1.f);
            float cw = 0.5f * (cospif(d * 0.1f) + 1.f);
            float t  = d * ((float)PGRID / 10.f);
            u = (int)t;
            if (u > PGRID) u = PGRID;
            float s = t - (float)u;
            w1v = s * cw;
            w0  = cw - w1v;
        }
        eu[e]  = u;
        ew0[e] = w0;
        ew1[e] = w1v;
    }
    if (e < PTAB * KPAD) {
        int p = e >> 6, g = e & 63;
        float v = 0.f;
        if (g < NG) {
            float d   = (float)p * (10.f / (float)PGRID);
            float off = (float)g * (10.f / 49.f);
            float df  = d - off;
            v = expf(-12.005f * df * df);        // -0.5/(10/49)^2
        }
        rb64[e] = v;
    }
    if (e < W1P_TOT) {
        int L  = e / (KPAD * HID);
        int rr = (e / HID) % KPAD;
        int cc = e % HID;
        w1p[e] = (rr < NG) ? w1[(size_t)L * NG * HID + rr * HID + cc] : 0.f;
    }
}

// ---------------- atom embedding gather ----------------
__global__ void embed_k(const int* __restrict__ z, const float* __restrict__ emb,
                        float* __restrict__ h) {
    int idx = blockIdx.x * blockDim.x + threadIdx.x;
    if (idx >= NTOT * HID) return;
    int n = idx / HID, f = idx % HID;
    h[idx] = emb[z[n] * HID + f];
}

// ---------------- 64x64 tf32 GEMM, pipelined, 8 warps, z-batched ----------------
// C_z = op(A_z[M,K] @ W_z[K,N] (+bias_z)) ; FL_H16 writes __half via packed half2
__global__ __launch_bounds__(256) void gemm_tc(
        const float* __restrict__ A, const float* __restrict__ W,
        const float* __restrict__ bias, float* __restrict__ C,
        int M, int N, int K, int flags,
        int zsA, int zsW, int zsB, int zsC) {
    __shared__ uint32_t As[32][72];
    __shared__ uint32_t Bs[32][72];

    int zz = blockIdx.z;
    A += (size_t)zz * zsA;
    W += (size_t)zz * zsW;
    const float* biasz = bias ? bias + (size_t)zz * zsB : bias;
    float*  Cf = C + (size_t)zz * zsC;
    __half* Ch = (__half*)C + (size_t)zz * zsC;

    int tid  = threadIdx.x;
    int row0 = blockIdx.y * 64, col0 = blockIdx.x * 64;
    int warp = tid >> 5, lane = tid & 31;
    int wm = (warp >> 2) * 32;
    int wn = (warp & 3) * 16;
    int g = lane >> 2, tig = lane & 3;

    bool k16 = ((K & 3) == 0);

    float c[2][2][4];
#pragma unroll
    for (int mi = 0; mi < 2; mi++)
#pragma unroll
        for (int ni = 0; ni < 2; ni++)
#pragma unroll
            for (int q = 0; q < 4; q++) c[mi][ni][q] = 0.f;

    float a_st[2][4], b_st[2][4];

    auto ldA = [&](int k0) {
#pragma unroll
        for (int l = 0; l < 2; l++) {
            int idx = tid + l * 256;
            int r   = idx >> 3;
            int c4  = idx & 7;
            int grow = row0 + r;
            int kg   = k0 + c4 * 4;
            float v0 = 0.f, v1 = 0.f, v2 = 0.f, v3 = 0.f;
            if (grow < M) {
                if (k16 && (kg + 3 < K)) {
                    float4 t = *(const float4*)(A + (size_t)grow * K + kg);
                    v0 = t.x; v1 = t.y; v2 = t.z; v3 = t.w;
                } else {
                    if (kg + 0 < K) v0 = A[(size_t)grow * K + kg + 0];
                    if (kg + 1 < K) v1 = A[(size_t)grow * K + kg + 1];
                    if (kg + 2 < K) v2 = A[(size_t)grow * K + kg + 2];
                    if (kg + 3 < K) v3 = A[(size_t)grow * K + kg + 3];
                }
            }
            a_st[l][0] = v0; a_st[l][1] = v1; a_st[l][2] = v2; a_st[l][3] = v3;
        }
    };
    auto ldB = [&](int k0) {
#pragma unroll
        for (int l = 0; l < 2; l++) {
            int idx = tid + l * 256;
            int kk  = idx >> 4;
            int c16 = idx & 15;
            int kg  = k0 + kk;
            int gc  = col0 + c16 * 4;
            float v0 = 0.f, v1 = 0.f, v2 = 0.f, v3 = 0.f;
            if (kg < K) {
                if (((N & 3) == 0) && (gc + 3 < N)) {
                    float4 t = *(const float4*)(W + (size_t)kg * N + gc);
                    v0 = t.x; v1 = t.y; v2 = t.z; v3 = t.w;
                } else {
                    if (gc + 0 < N) v0 = W[(size_t)kg * N + gc + 0];
                    if (gc + 1 < N) v1 = W[(size_t)kg * N + gc + 1];
                    if (gc + 2 < N) v2 = W[(size_t)kg * N + gc + 2];
                    if (gc + 3 < N) v3 = W[(size_t)kg * N + gc + 3];
                }
            }
            b_st[l][0] = v0; b_st[l][1] = v1; b_st[l][2] = v2; b_st[l][3] = v3;
        }
    };
    auto sts = [&]() {
#pragma unroll
        for (int l = 0; l < 2; l++) {
            int idx = tid + l * 256;
            int r   = idx >> 3;
            int c4  = idx & 7;
#pragma unroll
            for (int q = 0; q < 4; q++) As[c4 * 4 + q][r] = f2tf(a_st[l][q]);
            int kk  = idx >> 4;
            int c16 = idx & 15;
#pragma unroll
            for (int q = 0; q < 4; q++) Bs[kk][c16 * 4 + q] = f2tf(b_st[l][q]);
        }
    };

    int nk = (K + 31) >> 5;

    ldA(0); ldB(0);
    sts();
    __syncthreads();

    for (int kb = 0; kb < nk; kb++) {
        bool more = (kb + 1 < nk);
        if (more) { ldA((kb + 1) << 5); ldB((kb + 1) << 5); }

#pragma unroll
        for (int ks = 0; ks < 4; ks++) {
            int kb8 = ks * 8;
            uint32_t a[2][4], b[2][2];
#pragma unroll
            for (int mi = 0; mi < 2; mi++) {
                int m = wm + mi * 16;
                a[mi][0] = As[kb8 + tig    ][m + g    ];
                a[mi][1] = As[kb8 + tig    ][m + g + 8];
                a[mi][2] = As[kb8 + tig + 4][m + g    ];
                a[mi][3] = As[kb8 + tig + 4][m + g + 8];
            }
#pragma unroll
            for (int ni = 0; ni < 2; ni++) {
                int n = wn + ni * 8;
                b[ni][0] = Bs[kb8 + tig    ][n + g];
                b[ni][1] = Bs[kb8 + tig + 4][n + g];
            }
#pragma unroll
            for (int mi = 0; mi < 2; mi++)
#pragma unroll
                for (int ni = 0; ni < 2; ni++) {
                    asm volatile(
                        "mma.sync.aligned.m16n8k8.row.col.f32.tf32.tf32.f32 "
                        "{%0,%1,%2,%3}, {%4,%5,%6,%7}, {%8,%9}, {%0,%1,%2,%3};\n"
                        : "+f"(c[mi][ni][0]), "+f"(c[mi][ni][1]),
                          "+f"(c[mi][ni][2]), "+f"(c[mi][ni][3])
                        : "r"(a[mi][0]), "r"(a[mi][1]), "r"(a[mi][2]), "r"(a[mi][3]),
                          "r"(b[ni][0]), "r"(b[ni][1]));
                }
        }
        if (more) {
            __syncthreads();
            sts();
            __syncthreads();
        }
    }

    // ---- epilogue: paired even/odd columns ----
#pragma unroll
    for (int mi = 0; mi < 2; mi++) {
#pragma unroll
        for (int h01 = 0; h01 < 2; h01++) {
            int row = row0 + wm + mi * 16 + g + h01 * 8;
            if (row >= M) continue;
#pragma unroll
            for (int ni = 0; ni < 2; ni++) {
                int col = col0 + wn + ni * 8 + tig * 2;
                if (col >= N) continue;
                float v0 = c[mi][ni][h01 * 2 + 0];
                float v1 = c[mi][ni][h01 * 2 + 1];
                if (flags & FL_BIAS) { v0 += biasz[col]; v1 += biasz[col + 1]; }
                if (flags & FL_SSP)  { v0 = sspf(v0);    v1 = sspf(v1); }
                size_t idx = (size_t)row * N + col;
                if (flags & FL_H16) {
                    *(__half2*)(Ch + idx) = __floats2half2_rn(v0, v1);
                } else {
                    if (flags & FL_RES) { v0 += Cf[idx]; v1 += Cf[idx + 1]; }
                    Cf[idx]     = v0;
                    Cf[idx + 1] = v1;
                }
            }
        }
    }
}

// ---------------- message: fp16 table + fp16 x, direct-LDG (R14 best) ----------------
__global__ __launch_bounds__(128) void message_h(
        const int* __restrict__ eu, const float* __restrict__ ew0,
        const float* __restrict__ ew1,
        const __half* __restrict__ tab, const __half* __restrict__ xj,
        float* __restrict__ m) {
    int bi = blockIdx.x;
    int b  = bi >> 5;
    int tid = threadIdx.x;

    __shared__ int   us[NA];
    __shared__ float w0s[NA], w1s[NA];
    if (tid < NA) {
        int e = bi * NA + tid;
        us[tid]  = eu[e];
        w0s[tid] = ew0[e];
        w1s[tid] = ew1[e];
    }
    __syncthreads();

    float4 acc0 = make_float4(0.f, 0.f, 0.f, 0.f);
    float4 acc1 = make_float4(0.f, 0.f, 0.f, 0.f);
    const __half* xb = xj + (size_t)(b * NA) * HID;

#pragma unroll 4
    for (int j = 0; j < NA; j++) {
        int   u  = us[j];
        float w0 = w0s[j], w1 = w1s[j];
        const __half* T0 = tab + (size_t)u * HID;
        const __half* xr = xb + (size_t)j * HID;
        {
            uint2 r0 = *(const uint2*)(T0 + tid * 4);
            uint2 r1 = *(const uint2*)(T0 + HID + tid * 4);
            uint2 xw = *(const uint2*)(xr + tid * 4);
            float2 a0 = __half22float2(*(__half2*)&r0.x);
            float2 a1 = __half22float2(*(__half2*)&r0.y);
            float2 b0 = __half22float2(*(__half2*)&r1.x);
            float2 b1 = __half22float2(*(__half2*)&r1.y);
            float2 x0 = __half22float2(*(__half2*)&xw.x);
            float2 x1 = __half22float2(*(__half2*)&xw.y);
            acc0.x = fmaf(fmaf(w0, a0.x, w1 * b0.x), x0.x, acc0.x);
            acc0.y = fmaf(fmaf(w0, a0.y, w1 * b0.y), x0.y, acc0.y);
            acc0.z = fmaf(fmaf(w0, a1.x, w1 * b1.x), x1.x, acc0.z);
            acc0.w = fmaf(fmaf(w0, a1.y, w1 * b1.y), x1.y, acc0.w);
        }
        if (tid < 22) {
            int q = tid + 128;
            uint2 r0 = *(const uint2*)(T0 + q * 4);
            uint2 r1 = *(const uint2*)(T0 + HID + q * 4);
            uint2 xw = *(const uint2*)(xr + q * 4);
            float2 a0 = __half22float2(*(__half2*)&r0.x);
            float2 a1 = __half22float2(*(__half2*)&r0.y);
            float2 b0 = __half22float2(*(__half2*)&r1.x);
            float2 b1 = __half22float2(*(__half2*)&r1.y);
            float2 x0 = __half22float2(*(__half2*)&xw.x);
            float2 x1 = __half22float2(*(__half2*)&xw.y);
            acc1.x = fmaf(fmaf(w0, a0.x, w1 * b0.x), x0.x, acc1.x);
            acc1.y = fmaf(fmaf(w0, a0.y, w1 * b0.y), x0.y, acc1.y);
            acc1.z = fmaf(fmaf(w0, a1.x, w1 * b1.x), x1.x, acc1.z);
            acc1.w = fmaf(fmaf(w0, a1.y, w1 * b1.y), x1.y, acc1.w);
        }
    }
    float4* mr = (float4*)(m + (size_t)bi * HID);
    mr[tid] = acc0;
    if (tid < 22) mr[tid + 128] = acc1;
}

// ---------------- per-graph mean pool ----------------
__global__ void pool_k(const float* __restrict__ h, float* __restrict__ pool) {
    int idx = blockIdx.x * blockDim.x + threadIdx.x;
    if (idx >= BG * HID) return;
    int b = idx / HID, f = idx % HID;
    float s = 0.f;
#pragma unroll
    for (int i = 0; i < NA; i++) s += h[(size_t)(b * NA + i) * HID + f];
    pool[idx] = s * (1.f / (float)NA);
}

// ---------------- host launch ----------------
extern "C" void kernel_launch(void* const* d_in, const int* in_sizes, int n_in,
                              void* d_out, int out_size) {
    const int*   z    = (const int*)  d_in[0];
    const float* pos  = (const float*)d_in[1];
    const float* emb  = (const float*)d_in[3];
    const float* w1   = (const float*)d_in[4];
    const float* b1   = (const float*)d_in[5];
    const float* w2   = (const float*)d_in[6];
    const float* b2   = (const float*)d_in[7];
    const float* l1w  = (const float*)d_in[8];
    const float* l2w  = (const float*)d_in[9];
    const float* l2b  = (const float*)d_in[10];
    const float* lw   = (const float*)d_in[11];
    const float* lb   = (const float*)d_in[12];
    const float* pw   = (const float*)d_in[13];
    const float* pb   = (const float*)d_in[14];
    float* out = (float*)d_out;

    float* S = nullptr;
    cudaGetSymbolAddress((void**)&S, g_scratch);
    float*  H   = S + O_H;
    __half* XJh = (__half*)(S + O_XJ);
    float*  MM  = S + O_M;
    float*  T1  = S + O_T1;
    float*  TAa = S + O_TA_ALL;
    __half* TBa = (__half*)(S + O_TB_ALL);
    float*  RB  = S + O_RB64;
    float*  W1P = S + O_W1P;
    int*    EU  = (int*)(S + O_EU);
    float*  E0  = S + O_EW0;
    float*  E1  = S + O_EW1;
    float*  PL  = S + O_POOL;

    init_k <<<(INIT_TOT + 255) / 256, 256>>>(pos, w1, EU, E0, E1, RB, W1P);
    embed_k<<<(NTOT * HID + 255) / 256, 256>>>(z, emb, H);

    dim3 gN((HID + 63) / 64, (NTOT + 63) / 64);        // (10, 32)
    dim3 gTB((HID + 63) / 64, (PTAB + 63) / 64, NL);   // (10, 17, 6) batched

    // ---- all-layer filter-table build (2 launches) ----
    gemm_tc<<<gTB, 256>>>(RB, W1P, b1, TAa, PTAB, HID, KPAD, FL_BIAS | FL_SSP,
                          0, KPAD * HID, HID, TABL);
    gemm_tc<<<gTB, 256>>>(TAa, w2, b2, (float*)TBa, PTAB, HID, HID,
                          FL_BIAS | FL_H16, TABL, HID * HID, HID, TABL);

    for (int L = 0; L < NL; L++) {
        const float* l1wL = l1w + (size_t)L * HID * HID;
        const float* l2wL = l2w + (size_t)L * HID * HID;
        const float* l2bL = l2b + (size_t)L * HID;
        const float* lwL  = lw  + (size_t)L * HID * HID;
        const float* lbL  = lb  + (size_t)L * HID;
        const __half* tabL = TBa + (size_t)L * TABL;

        // xj = fp16(h @ lin1) (no bias)
        gemm_tc<<<gN, 256>>>(H, l1wL, nullptr, (float*)XJh, NTOT, HID, HID,
                             FL_H16, 0, 0, 0, 0);
        // fp16 interpolate + scatter-reduce message
        message_h<<<NTOT, 128>>>(EU, E0, E1, tabL, XJh, MM);
        // v = ssp(m @ l2w + l2b) @ lw + lb ; h += v
        gemm_tc<<<gN, 256>>>(MM, l2wL, l2bL, T1, NTOT, HID, HID,
                             FL_BIAS | FL_SSP, 0, 0, 0, 0);
        gemm_tc<<<gN, 256>>>(T1, lwL,  lbL,  H,  NTOT, HID, HID,
                             FL_BIAS | FL_RES, 0, 0, 0, 0);
    }

    pool_k<<<(BG * HID + 255) / 256, 256>>>(H, PL);
    gemm_tc<<<dim3((HID + 63) / 64, 1), 256>>>(PL, pw, pb, out, BG, HID, HID,
                                               FL_BIAS, 0, 0, 0, 0);
}